// round 3
// baseline (speedup 1.0000x reference)
#include <cuda_runtime.h>
#include <cuda_bf16.h>
#include <float.h>

// Segmented 3-NN cosine-consistency loss, column-split edition.
// Each row's scan over the segment is split across CHUNKS=8 threads
// (512 columns each at seg=4096); per-thread sorted top-3 lists are merged
// with width-8 shuffle rounds using lexicographic (d, j) compare, which
// reproduces jax.lax.top_k's lower-index tie-break. chunk==0 thread of each
// row then computes the neighbor-cosine loss term; deterministic two-stage
// reduction produces the scalar.

#define THREADS 256
#define CHUNKS  8
#define ROWSPB  (THREADS / CHUNKS)   // 32 rows per block
#define SEG_MAX 4096                 // smem tile capacity (points)

__device__ float g_partials[4096];

__device__ __forceinline__ float dot3(float ax, float ay, float az,
                                      float bx, float by, float bz) {
    return fmaf(ax, bx, fmaf(ay, by, az * bz));
}

// lexicographic (d, j) compare: smaller d wins; equal d -> smaller j wins
__device__ __forceinline__ bool lessDJ(float da, int ja, float db, int jb) {
    return (da < db) || (da == db && ja < jb);
}

// insert (d, j) into sorted top-3 (D0<=D1<=D2) with lex tie-break
__device__ __forceinline__ void ins3(float d, int j,
                                     float& D0, int& I0,
                                     float& D1, int& I1,
                                     float& D2, int& I2) {
    if (lessDJ(d, j, D2, I2)) {
        if (lessDJ(d, j, D1, I1)) {
            D2 = D1; I2 = I1;
            if (lessDJ(d, j, D0, I0)) { D1 = D0; I1 = I0; D0 = d; I0 = j; }
            else                      { D1 = d;  I1 = j; }
        } else { D2 = d; I2 = j; }
    }
}

__global__ void __launch_bounds__(THREADS)
knn_loss_kernel(const float* __restrict__ pred,
                const float* __restrict__ coord,
                const float* __restrict__ target,
                int seg, int nseg, int blocksPerSeg) {
    extern __shared__ float4 s_c[];   // SEG_MAX entries: (-2x,-2y,-2z,sq)

    const int segIdx  = blockIdx.x / blocksPerSeg;
    const int rowBase = (blockIdx.x % blocksPerSeg) * ROWSPB;
    const int rowIn   = threadIdx.x >> 3;       // /CHUNKS
    const int chunk   = threadIdx.x & (CHUNKS - 1);
    const int i       = rowBase + rowIn;        // local row in segment
    const bool active = (i < seg);
    const long segOff = (long)segIdx * seg;
    const long gi     = segOff + i;

    // this thread's column range within the segment
    const int cLen = (seg + CHUNKS - 1) / CHUNKS;
    const int cBeg = chunk * cLen;
    const int cEnd = min(seg, cBeg + cLen);

    float xi = 0.f, yi = 0.f, zi = 0.f, sqi = 0.f;
    if (active) {
        xi  = coord[3 * gi + 0];
        yi  = coord[3 * gi + 1];
        zi  = coord[3 * gi + 2];
        sqi = xi * xi + yi * yi + zi * zi;
    }

    float D0 = FLT_MAX, D1 = FLT_MAX, D2 = FLT_MAX;
    int   I0 = -1, I1 = -1, I2 = -1;

    for (int jb = 0; jb < seg; jb += SEG_MAX) {
        const int tlen = min(SEG_MAX, seg - jb);

        __syncthreads();
        for (int t = threadIdx.x; t < tlen; t += blockDim.x) {
            const long gj = segOff + jb + t;
            float x = coord[3 * gj + 0];
            float y = coord[3 * gj + 1];
            float z = coord[3 * gj + 2];
            s_c[t] = make_float4(-2.f * x, -2.f * y, -2.f * z,
                                 x * x + y * y + z * z);
        }
        __syncthreads();

        const int tBeg = max(cBeg - jb, 0);
        const int tEnd = min(cEnd - jb, tlen);
        if (active && tBeg < tEnd) {
            float thr = D2 - sqi;   // e-space threshold: e < thr <=> d2raw < D2
            #pragma unroll 4
            for (int t = tBeg; t < tEnd; t++) {
                const float4 c = s_c[t];
                const float e = fmaf(c.x, xi, fmaf(c.y, yi, fmaf(c.z, zi, c.w)));
                if (e < thr) {
                    const int j = jb + t;
                    if (j != i) {
                        const float d = fmaxf(sqi + e, 0.0f);
                        ins3(d, j, D0, I0, D1, I1, D2, I2);
                        thr = D2 - sqi;
                    }
                }
            }
        }
    }

    // ---- merge the 8 chunk-local top-3 lists (width-8 shuffle tree) ----
    #pragma unroll
    for (int off = 4; off >= 1; off >>= 1) {
        float b0 = __shfl_down_sync(0xffffffffu, D0, off, CHUNKS);
        int   k0 = __shfl_down_sync(0xffffffffu, I0, off, CHUNKS);
        float b1 = __shfl_down_sync(0xffffffffu, D1, off, CHUNKS);
        int   k1 = __shfl_down_sync(0xffffffffu, I1, off, CHUNKS);
        float b2 = __shfl_down_sync(0xffffffffu, D2, off, CHUNKS);
        int   k2 = __shfl_down_sync(0xffffffffu, I2, off, CHUNKS);
        // insert the partner's sorted list in ascending order
        ins3(b0, k0, D0, I0, D1, I1, D2, I2);
        ins3(b1, k1, D0, I0, D1, I1, D2, I2);
        ins3(b2, k2, D0, I0, D1, I1, D2, I2);
    }

    // ---- epilogue: neighbor similarity loss (chunk-0 lane of each row) ----
    float acc = 0.0f;
    if (active && chunk == 0) {
        float px = pred[3 * gi + 0], py = pred[3 * gi + 1], pz = pred[3 * gi + 2];
        float inpv = sqrtf(px * px + py * py + pz * pz + 1e-8f) + 1e-10f;
        float pnx = px / inpv, pny = py / inpv, pnz = pz / inpv;

        float tx = target[3 * gi + 0], ty = target[3 * gi + 1], tz = target[3 * gi + 2];

        const int nbr[3] = { I0, I1, I2 };
        #pragma unroll
        for (int k = 0; k < 3; k++) {
            const long gj = segOff + nbr[k];
            float qx = pred[3 * gj + 0], qy = pred[3 * gj + 1], qz = pred[3 * gj + 2];
            float inq = sqrtf(qx * qx + qy * qy + qz * qz + 1e-8f) + 1e-10f;
            float sim = fminf(fabsf(dot3(qx / inq, qy / inq, qz / inq,
                                         pnx, pny, pnz)), 1.0f);

            float ux = target[3 * gj + 0], uy = target[3 * gj + 1], uz = target[3 * gj + 2];
            float tsim = fminf(fabsf(dot3(ux, uy, uz, tx, ty, tz)), 1.0f);

            float diff = sim - tsim;
            acc = fmaf(diff, diff, acc);
        }
    }

    // ---- block reduction (deterministic) ----
    __shared__ float red[THREADS];
    red[threadIdx.x] = acc;
    __syncthreads();
    #pragma unroll
    for (int s = THREADS / 2; s > 0; s >>= 1) {
        if (threadIdx.x < s) red[threadIdx.x] += red[threadIdx.x + s];
        __syncthreads();
    }
    if (threadIdx.x == 0) g_partials[blockIdx.x] = red[0];
}

__global__ void __launch_bounds__(THREADS)
finalize_kernel(float* __restrict__ out, int nblocks, float invCount) {
    __shared__ float red[THREADS];
    float s = 0.0f;
    for (int b = threadIdx.x; b < nblocks; b += THREADS) s += g_partials[b];
    red[threadIdx.x] = s;
    __syncthreads();
    #pragma unroll
    for (int st = THREADS / 2; st > 0; st >>= 1) {
        if (threadIdx.x < st) red[threadIdx.x] += red[threadIdx.x + st];
        __syncthreads();
    }
    if (threadIdx.x == 0) out[0] = red[0] * invCount;
}

extern "C" void kernel_launch(void* const* d_in, const int* in_sizes, int n_in,
                              void* d_out, int out_size) {
    const float* pred   = (const float*)d_in[0];
    const float* coord  = (const float*)d_in[1];
    const float* target = (const float*)d_in[2];
    const int    nseg   = in_sizes[3];           // nums has nseg elements
    const int    npts   = in_sizes[0] / 3;
    const int    seg    = npts / nseg;

    const int blocksPerSeg = (seg + ROWSPB - 1) / ROWSPB;
    const int nblocks      = nseg * blocksPerSeg;
    const size_t smemBytes = (size_t)min(seg, SEG_MAX) * sizeof(float4);

    static bool attrDone = false;
    if (!attrDone) {
        cudaFuncSetAttribute(knn_loss_kernel,
                             cudaFuncAttributeMaxDynamicSharedMemorySize,
                             (int)((size_t)SEG_MAX * sizeof(float4)));
        attrDone = true;
    }

    knn_loss_kernel<<<nblocks, THREADS, smemBytes>>>(pred, coord, target,
                                                     seg, nseg, blocksPerSeg);

    const float invCount = 1.0f / ((float)nseg * (float)seg * 3.0f);
    finalize_kernel<<<1, THREADS>>>((float*)d_out, nblocks, invCount);
}

// round 5
// speedup vs baseline: 3.5598x; 3.5598x over previous
#include <cuda_runtime.h>
#include <cuda_bf16.h>
#include <float.h>

// Segmented 3-NN cosine-consistency loss, interleaved column-split edition.
// Each row's candidate scan is split across CHUNKS=8 lanes with an
// INTERLEAVED stride-8 pattern (t = chunk, chunk+8, ...): a warp's 8 chunk
// lanes read 8 consecutive float4s (128 contiguous bytes) from smem ->
// conflict-free, with 4-row broadcast on top. Per-lane sorted top-3 lists
// merge via width-8 shuffle rounds with lexicographic (d, j) compare,
// reproducing jax.lax.top_k's lower-index tie-break independent of scan
// order. chunk-0 lane of each row computes the neighbor-cosine loss term;
// deterministic two-stage reduction produces the scalar.

#define THREADS 256
#define CHUNKS  8
#define ROWSPB  (THREADS / CHUNKS)   // 32 rows per block
#define SEG_MAX 4096                 // smem tile capacity (points)

__device__ float g_partials[4096];

__device__ __forceinline__ float dot3(float ax, float ay, float az,
                                      float bx, float by, float bz) {
    return fmaf(ax, bx, fmaf(ay, by, az * bz));
}

// lexicographic (d, j) compare: smaller d wins; equal d -> smaller j wins
__device__ __forceinline__ bool lessDJ(float da, int ja, float db, int jb) {
    return (da < db) || (da == db && ja < jb);
}

// insert (d, j) into sorted top-3 (D0<=D1<=D2) with lex tie-break
__device__ __forceinline__ void ins3(float d, int j,
                                     float& D0, int& I0,
                                     float& D1, int& I1,
                                     float& D2, int& I2) {
    if (lessDJ(d, j, D2, I2)) {
        if (lessDJ(d, j, D1, I1)) {
            D2 = D1; I2 = I1;
            if (lessDJ(d, j, D0, I0)) { D1 = D0; I1 = I0; D0 = d; I0 = j; }
            else                      { D1 = d;  I1 = j; }
        } else { D2 = d; I2 = j; }
    }
}

__global__ void __launch_bounds__(THREADS)
knn_loss_kernel(const float* __restrict__ pred,
                const float* __restrict__ coord,
                const float* __restrict__ target,
                int seg, int nseg, int blocksPerSeg) {
    extern __shared__ float4 s_c[];   // up to SEG_MAX entries: (-2x,-2y,-2z,sq)

    const int segIdx  = blockIdx.x / blocksPerSeg;
    const int rowBase = (blockIdx.x % blocksPerSeg) * ROWSPB;
    const int rowIn   = threadIdx.x >> 3;        // / CHUNKS
    const int chunk   = threadIdx.x & (CHUNKS - 1);
    const int i       = rowBase + rowIn;         // local row in segment
    const bool active = (i < seg);
    const long segOff = (long)segIdx * seg;
    const long gi     = segOff + i;

    float xi = 0.f, yi = 0.f, zi = 0.f, sqi = 0.f;
    if (active) {
        xi  = coord[3 * gi + 0];
        yi  = coord[3 * gi + 1];
        zi  = coord[3 * gi + 2];
        sqi = xi * xi + yi * yi + zi * zi;
    }

    float D0 = FLT_MAX, D1 = FLT_MAX, D2 = FLT_MAX;
    int   I0 = -1, I1 = -1, I2 = -1;

    for (int jb = 0; jb < seg; jb += SEG_MAX) {
        const int tlen = min(SEG_MAX, seg - jb);

        __syncthreads();
        for (int t = threadIdx.x; t < tlen; t += blockDim.x) {
            const long gj = segOff + jb + t;
            float x = coord[3 * gj + 0];
            float y = coord[3 * gj + 1];
            float z = coord[3 * gj + 2];
            s_c[t] = make_float4(-2.f * x, -2.f * y, -2.f * z,
                                 x * x + y * y + z * z);
        }
        __syncthreads();

        if (active) {
            float thr = D2 - sqi;   // e-space threshold: e < thr <=> d2raw < D2
            // interleaved: lane 'chunk' handles t = chunk, chunk+8, ...
            // -> warp reads 8 consecutive float4s: conflict-free broadcast
            #pragma unroll 4
            for (int t = chunk; t < tlen; t += CHUNKS) {
                const float4 c = s_c[t];
                const float e = fmaf(c.x, xi, fmaf(c.y, yi, fmaf(c.z, zi, c.w)));
                if (e < thr) {
                    const int j = jb + t;
                    if (j != i) {
                        const float d = fmaxf(sqi + e, 0.0f);
                        ins3(d, j, D0, I0, D1, I1, D2, I2);
                        thr = D2 - sqi;
                    }
                }
            }
        }
    }

    // ---- merge the 8 chunk-local top-3 lists (width-8 shuffle tree) ----
    #pragma unroll
    for (int off = 4; off >= 1; off >>= 1) {
        float b0 = __shfl_down_sync(0xffffffffu, D0, off, CHUNKS);
        int   k0 = __shfl_down_sync(0xffffffffu, I0, off, CHUNKS);
        float b1 = __shfl_down_sync(0xffffffffu, D1, off, CHUNKS);
        int   k1 = __shfl_down_sync(0xffffffffu, I1, off, CHUNKS);
        float b2 = __shfl_down_sync(0xffffffffu, D2, off, CHUNKS);
        int   k2 = __shfl_down_sync(0xffffffffu, I2, off, CHUNKS);
        ins3(b0, k0, D0, I0, D1, I1, D2, I2);
        ins3(b1, k1, D0, I0, D1, I1, D2, I2);
        ins3(b2, k2, D0, I0, D1, I1, D2, I2);
    }

    // ---- epilogue: neighbor similarity loss (chunk-0 lane of each row) ----
    float acc = 0.0f;
    if (active && chunk == 0) {
        float px = pred[3 * gi + 0], py = pred[3 * gi + 1], pz = pred[3 * gi + 2];
        float inpv = sqrtf(px * px + py * py + pz * pz + 1e-8f) + 1e-10f;
        float pnx = px / inpv, pny = py / inpv, pnz = pz / inpv;

        float tx = target[3 * gi + 0], ty = target[3 * gi + 1], tz = target[3 * gi + 2];

        const int nbr[3] = { I0, I1, I2 };
        #pragma unroll
        for (int k = 0; k < 3; k++) {
            const long gj = segOff + nbr[k];
            float qx = pred[3 * gj + 0], qy = pred[3 * gj + 1], qz = pred[3 * gj + 2];
            float inq = sqrtf(qx * qx + qy * qy + qz * qz + 1e-8f) + 1e-10f;
            float sim = fminf(fabsf(dot3(qx / inq, qy / inq, qz / inq,
                                         pnx, pny, pnz)), 1.0f);

            float ux = target[3 * gj + 0], uy = target[3 * gj + 1], uz = target[3 * gj + 2];
            float tsim = fminf(fabsf(dot3(ux, uy, uz, tx, ty, tz)), 1.0f);

            float diff = sim - tsim;
            acc = fmaf(diff, diff, acc);
        }
    }

    // ---- block reduction (deterministic) ----
    __shared__ float red[THREADS];
    red[threadIdx.x] = acc;
    __syncthreads();
    #pragma unroll
    for (int s = THREADS / 2; s > 0; s >>= 1) {
        if (threadIdx.x < s) red[threadIdx.x] += red[threadIdx.x + s];
        __syncthreads();
    }
    if (threadIdx.x == 0) g_partials[blockIdx.x] = red[0];
}

__global__ void __launch_bounds__(THREADS)
finalize_kernel(float* __restrict__ out, int nblocks, float invCount) {
    __shared__ float red[THREADS];
    float s = 0.0f;
    for (int b = threadIdx.x; b < nblocks; b += THREADS) s += g_partials[b];
    red[threadIdx.x] = s;
    __syncthreads();
    #pragma unroll
    for (int st = THREADS / 2; st > 0; st >>= 1) {
        if (threadIdx.x < st) red[threadIdx.x] += red[threadIdx.x + st];
        __syncthreads();
    }
    if (threadIdx.x == 0) out[0] = red[0] * invCount;
}

extern "C" void kernel_launch(void* const* d_in, const int* in_sizes, int n_in,
                              void* d_out, int out_size) {
    const float* pred   = (const float*)d_in[0];
    const float* coord  = (const float*)d_in[1];
    const float* target = (const float*)d_in[2];
    const int    nseg   = in_sizes[3];           // nums has nseg elements
    const int    npts   = in_sizes[0] / 3;
    const int    seg    = npts / nseg;

    const int blocksPerSeg = (seg + ROWSPB - 1) / ROWSPB;
    const int nblocks      = nseg * blocksPerSeg;
    const size_t smemBytes = (size_t)min(seg, SEG_MAX) * sizeof(float4);

    static bool attrDone = false;
    if (!attrDone) {
        cudaFuncSetAttribute(knn_loss_kernel,
                             cudaFuncAttributeMaxDynamicSharedMemorySize,
                             (int)((size_t)SEG_MAX * sizeof(float4)));
        attrDone = true;
    }

    knn_loss_kernel<<<nblocks, THREADS, smemBytes>>>(pred, coord, target,
                                                     seg, nseg, blocksPerSeg);

    const float invCount = 1.0f / ((float)nseg * (float)seg * 3.0f);
    finalize_kernel<<<1, THREADS>>>((float*)d_out, nblocks, invCount);
}

// round 8
// speedup vs baseline: 4.3342x; 1.2175x over previous
#include <cuda_runtime.h>
#include <cuda_bf16.h>
#include <float.h>

// Segmented 3-NN cosine-consistency loss, column-block split edition.
//
// Kernel 1 (knn_partial): grid = nseg * rowTiles * NCB blocks. Each block
//   handles 256 rows x one column strip (colT points staged in smem as
//   (-2x,-2y,-2z,|c|^2)). One thread = one row: all 32 lanes of a warp read
//   the SAME smem entry each iter (pure broadcast, conflict-free, 1 phase),
//   and per-thread top-3 insert events are rare (3*ln(colT) per thread), so
//   warp divergence is minimal. Top-3 is tracked in e-space
//   (e = |cj|^2 - 2 ci.cj; ordering by e == ordering by clamped d2).
//   Per-(row, colblock) sorted (e, j) triples go to __device__ scratch.
// Kernel 2 (merge_epilogue): one thread per row merges the NCB partial
//   lists in ascending colblock order with strict e-compare (reproduces
//   jax.lax.top_k's lower-index tie-break), then computes the
//   neighbor-cosine loss term and block-reduces.
// Kernel 3 (finalize): deterministic reduction of block partials.

#define T1      256
#define COLT    1024
#define MAXCB   16

__device__ float g_pe[32768 * MAXCB * 3];
__device__ int   g_pj[32768 * MAXCB * 3];
__device__ float g_partials[256];

__device__ __forceinline__ float dot3(float ax, float ay, float az,
                                      float bx, float by, float bz) {
    return fmaf(ax, bx, fmaf(ay, by, az * bz));
}

// strict-< sorted insert of (e, j) into (E0<=E1<=E2); earlier-inserted wins
// ties, which equals lower-j when candidates arrive in ascending-j order.
__device__ __forceinline__ void ins3e(float e, int j,
                                      float& E0, int& J0,
                                      float& E1, int& J1,
                                      float& E2, int& J2) {
    if (e < E1) {
        E2 = E1; J2 = J1;
        if (e < E0) { E1 = E0; J1 = J0; E0 = e; J0 = j; }
        else        { E1 = e;  J1 = j; }
    } else { E2 = e; J2 = j; }
}

__global__ void __launch_bounds__(T1)
knn_partial(const float* __restrict__ coord,
            int seg, int rowTiles, int NCB, int colT) {
    extern __shared__ float4 s_c[];   // colT entries

    const int cb      = blockIdx.x % NCB;
    const int tmp     = blockIdx.x / NCB;
    const int rowTile = tmp % rowTiles;
    const int segIdx  = tmp / rowTiles;
    const int i       = rowTile * T1 + threadIdx.x;   // local row
    const long segOff = (long)segIdx * seg;

    const int cBeg = cb * colT;
    const int tlen = min(seg - cBeg, colT);

    // stage column strip
    for (int t = threadIdx.x; t < tlen; t += T1) {
        const long gj = segOff + cBeg + t;
        float x = coord[3 * gj + 0];
        float y = coord[3 * gj + 1];
        float z = coord[3 * gj + 2];
        s_c[t] = make_float4(-2.f * x, -2.f * y, -2.f * z,
                             x * x + y * y + z * z);
    }
    __syncthreads();

    float E0 = FLT_MAX, E1 = FLT_MAX, E2 = FLT_MAX;
    int   J0 = -1, J1 = -1, J2 = -1;

    if (i < seg) {
        const long gi = segOff + i;
        const float xi = coord[3 * gi + 0];
        const float yi = coord[3 * gi + 1];
        const float zi = coord[3 * gi + 2];

        #pragma unroll 4
        for (int t = 0; t < tlen; t++) {
            const float4 c = s_c[t];
            const float e = fmaf(c.x, xi, fmaf(c.y, yi, fmaf(c.z, zi, c.w)));
            if (e < E2) {                  // rare: ~3*ln(colT) per thread
                const int j = cBeg + t;
                if (j != i) ins3e(e, j, E0, J0, E1, J1, E2, J2);
            }
        }

        const long base = ((segOff + i) * MAXCB + cb) * 3;
        g_pe[base + 0] = E0; g_pj[base + 0] = J0;
        g_pe[base + 1] = E1; g_pj[base + 1] = J1;
        g_pe[base + 2] = E2; g_pj[base + 2] = J2;
    }
}

__global__ void __launch_bounds__(T1)
merge_epilogue(const float* __restrict__ pred,
               const float* __restrict__ target,
               int seg, int NCB, int nrows) {
    const int r = blockIdx.x * T1 + threadIdx.x;   // global row
    float acc = 0.0f;

    if (r < nrows) {
        float E0 = FLT_MAX, E1 = FLT_MAX, E2 = FLT_MAX;
        int   J0 = -1, J1 = -1, J2 = -1;

        // ascending colblock order => ascending j => strict < is the
        // correct lower-index tie-break
        for (int cb = 0; cb < NCB; cb++) {
            const long base = ((long)r * MAXCB + cb) * 3;
            #pragma unroll
            for (int k = 0; k < 3; k++) {
                const float e = g_pe[base + k];
                if (e < E2) {
                    const int j = g_pj[base + k];
                    ins3e(e, j, E0, J0, E1, J1, E2, J2);
                }
            }
        }

        const int  segIdx = r / seg;
        const long segOff = (long)segIdx * seg;
        const long gi     = r;

        float px = pred[3 * gi + 0], py = pred[3 * gi + 1], pz = pred[3 * gi + 2];
        float inpv = sqrtf(px * px + py * py + pz * pz + 1e-8f) + 1e-10f;
        float pnx = px / inpv, pny = py / inpv, pnz = pz / inpv;

        float tx = target[3 * gi + 0], ty = target[3 * gi + 1], tz = target[3 * gi + 2];

        const int nbr[3] = { J0, J1, J2 };
        #pragma unroll
        for (int k = 0; k < 3; k++) {
            const long gj = segOff + nbr[k];
            float qx = pred[3 * gj + 0], qy = pred[3 * gj + 1], qz = pred[3 * gj + 2];
            float inq = sqrtf(qx * qx + qy * qy + qz * qz + 1e-8f) + 1e-10f;
            float sim = fminf(fabsf(dot3(qx / inq, qy / inq, qz / inq,
                                         pnx, pny, pnz)), 1.0f);

            float ux = target[3 * gj + 0], uy = target[3 * gj + 1], uz = target[3 * gj + 2];
            float tsim = fminf(fabsf(dot3(ux, uy, uz, tx, ty, tz)), 1.0f);

            float diff = sim - tsim;
            acc = fmaf(diff, diff, acc);
        }
    }

    __shared__ float red[T1];
    red[threadIdx.x] = acc;
    __syncthreads();
    #pragma unroll
    for (int s = T1 / 2; s > 0; s >>= 1) {
        if (threadIdx.x < s) red[threadIdx.x] += red[threadIdx.x + s];
        __syncthreads();
    }
    if (threadIdx.x == 0) g_partials[blockIdx.x] = red[0];
}

__global__ void __launch_bounds__(T1)
finalize_kernel(float* __restrict__ out, int nblocks, float invCount) {
    __shared__ float red[T1];
    float s = 0.0f;
    for (int b = threadIdx.x; b < nblocks; b += T1) s += g_partials[b];
    red[threadIdx.x] = s;
    __syncthreads();
    #pragma unroll
    for (int st = T1 / 2; st > 0; st >>= 1) {
        if (threadIdx.x < st) red[threadIdx.x] += red[threadIdx.x + st];
        __syncthreads();
    }
    if (threadIdx.x == 0) out[0] = red[0] * invCount;
}

extern "C" void kernel_launch(void* const* d_in, const int* in_sizes, int n_in,
                              void* d_out, int out_size) {
    const float* pred   = (const float*)d_in[0];
    const float* coord  = (const float*)d_in[1];
    const float* target = (const float*)d_in[2];
    const int    nseg   = in_sizes[3];           // nums has nseg elements
    const int    npts   = in_sizes[0] / 3;
    const int    seg    = npts / nseg;

    // column blocks: at most MAXCB strips; strip length >= 1024 when possible
    int NCB  = (seg + COLT - 1) / COLT;
    if (NCB > MAXCB) NCB = MAXCB;
    const int colT = (seg + NCB - 1) / NCB;

    const int rowTiles = (seg + T1 - 1) / T1;
    const int grid1    = nseg * rowTiles * NCB;
    const size_t smem1 = (size_t)colT * sizeof(float4);

    knn_partial<<<grid1, T1, smem1>>>(coord, seg, rowTiles, NCB, colT);

    const int nrows  = nseg * seg;
    const int grid2  = (nrows + T1 - 1) / T1;
    merge_epilogue<<<grid2, T1>>>(pred, target, seg, NCB, nrows);

    const float invCount = 1.0f / ((float)nrows * 3.0f);
    finalize_kernel<<<1, T1>>>((float*)d_out, grid2, invCount);
}